// round 12
// baseline (speedup 1.0000x reference)
#include <cuda_runtime.h>
#include <cuda_bf16.h>
#include <cstdint>

// SpikeEncoder: rates = sigmoid(x @ W^T + b); spikes = (u < rates)
// x: [256,512] f32, W: [2048,512] f32, b: [2048] f32, u: [256,100,2048] f32
// out: spikes [256*100*2048] f32, then rates [256*2048] f32

#define BATCH 256
#define INPUT_DIM 512
#define NUM_NEURONS 2048
#define TIME_STEPS 100

#define TBM 32                     // rows per pass-tile
#define TBN 64
#define TBK 32
#define NTILES (INPUT_DIM / TBK)   // 16
#define NPASS 2                    // 2 passes: rows 0..127, then 128..255

#define ROWF 36                    // padded floats per smem row (bank-bijective)
#define TILEF_A (TBM * ROWF)       // 1152
#define TILEF_B (TBN * ROWF)       // 2304
// buffer layout (floats): [Ahi | Alo | Bhi | Blo]
#define OFF_ALO  TILEF_A
#define OFF_BHI  (2 * TILEF_A)
#define OFF_BLO  (2 * TILEF_A + TILEF_B)
#define BUFF (2 * TILEF_A + 2 * TILEF_B)   // 6912 floats
#define SMEM_BYTES (2 * BUFF * 4)          // 55296 bytes

// Per-m-tile release counters (8 tiles of 32 rows; 32 n-blocks each)
__device__ unsigned g_cnt[8];

// fp32 -> tf32 split via mantissa mask: hi = one LOP3 (exact, hi+lo == v);
// lo rounded to tf32 (cvt.rna) -> representation err ~2^-21|v|.
__device__ __forceinline__ void tf32_split(float v, float& h, float& l) {
    const float hf = __uint_as_float(__float_as_uint(v) & 0xFFFFE000u);
    uint32_t lb;
    asm("cvt.rna.tf32.f32 %0, %1;" : "=r"(lb) : "f"(v - hf));
    h = hf;
    l = __uint_as_float(lb);
}

__device__ __forceinline__ void cvt_store(float* __restrict__ hi,
                                          float* __restrict__ lo,
                                          int off, float4 v) {
    float4 h, l;
    tf32_split(v.x, h.x, l.x);
    tf32_split(v.y, h.y, l.y);
    tf32_split(v.z, h.z, l.z);
    tf32_split(v.w, h.w, l.w);
    *(float4*)&hi[off] = h;
    *(float4*)&lo[off] = l;
}

// D += A(tf32, m16k8 row) x B(tf32, k8n8 col)
__device__ __forceinline__ void mma_tf32(float c[4],
                                         uint32_t a0, uint32_t a1,
                                         uint32_t a2, uint32_t a3,
                                         uint32_t b0, uint32_t b1) {
    asm volatile(
        "mma.sync.aligned.m16n8k8.row.col.f32.tf32.tf32.f32 "
        "{%0,%1,%2,%3}, {%4,%5,%6,%7}, {%8,%9}, {%0,%1,%2,%3};"
        : "+f"(c[0]), "+f"(c[1]), "+f"(c[2]), "+f"(c[3])
        : "r"(a0), "r"(a1), "r"(a2), "r"(a3), "r"(b0), "r"(b1));
}

// ---------------------------------------------------------------------------
// Kernel R: zero the release counters (graph-replay determinism).
// ---------------------------------------------------------------------------
__global__ void reset_kernel() {
    if (threadIdx.x < 8) g_cnt[threadIdx.x] = 0u;
}

// ---------------------------------------------------------------------------
// Kernel A: rates = sigmoid(x @ W^T + b), tf32 MMA, 3-term compensation
// (xh*Wh split even/odd-k8 into c0/c1 vs RZ bias; cross terms in cx;
// RN combine at epilogue). 32x64 tile per pass, TWO passes per block
// (rows by*32 then (by+4)*32) so rows 0..127 release at ~half the GEMM.
// After each pass: rates stores -> __syncthreads -> red.release on
// g_cnt[mtile]. PLC at kernel START so the spike grid co-schedules.
// grid (32, 4), 256 threads, 8 warps (mb = w&1 m16-blocks, nh = w>>1 n16).
// ---------------------------------------------------------------------------
__global__ __launch_bounds__(256)
void rates_kernel(const float* __restrict__ x,
                  const float* __restrict__ W,
                  const float* __restrict__ bias,
                  float* __restrict__ rates) {
#if __CUDA_ARCH__ >= 900
    cudaTriggerProgrammaticLaunchCompletion();
#endif
    extern __shared__ float sm[];

    const int tid  = threadIdx.x;
    const int warp = tid >> 5;
    const int lane = tid & 31;
    const int g = lane >> 2;       // fragment row
    const int q = lane & 3;        // fragment k/col
    const int mb = warp & 1;       // m16 block (0..1)
    const int nh = warp >> 1;      // n16 group (0..3)

    const int nBase = blockIdx.x * TBN;

    // Cooperative-load coords. A: 256 float4/tile (1/thread); B: 512 (2/thread)
    const int rowA = tid >> 3;             // 0..31
    const int kcA  = (tid & 7) * 4;
    int rowB[2], kcB[2];
#pragma unroll
    for (int l = 0; l < 2; l++) {
        const int f = tid + l * 256;
        rowB[l] = f >> 3;                  // 0..63
        kcB[l]  = (f & 7) * 4;
    }

    const int ar0 = (mb * 16 + g) * ROWF;
    const int ar1 = ar0 + 8 * ROWF;

    for (int pass = 0; pass < NPASS; pass++) {
        const int mtile = blockIdx.y + 4 * pass;   // 0..7
        const int mBase = mtile * TBM;

        // Prologue: tile 0 -> regs -> split -> smem buf 0
        float4 xa = *(const float4*)&x[(mBase + rowA) * INPUT_DIM + kcA];
        float4 wb[2];
#pragma unroll
        for (int l = 0; l < 2; l++)
            wb[l] = *(const float4*)&W[(nBase + rowB[l]) * INPUT_DIM + kcB[l]];
        {
            float* buf = sm;
            cvt_store(buf, buf + OFF_ALO, rowA * ROWF + kcA, xa);
#pragma unroll
            for (int l = 0; l < 2; l++)
                cvt_store(buf + OFF_BHI, buf + OFF_BLO, rowB[l] * ROWF + kcB[l], wb[l]);
        }
        __syncthreads();

        // Accumulators: c0/c1 = hi*hi even/odd k8 steps; cx = cross terms
        float c0[2][4], c1[2][4], cx[2][4];
#pragma unroll
        for (int nb = 0; nb < 2; nb++)
#pragma unroll
            for (int e = 0; e < 4; e++) { c0[nb][e] = 0.f; c1[nb][e] = 0.f; cx[nb][e] = 0.f; }

        for (int t = 0; t < NTILES; t++) {
            const float* buf = sm + (t & 1) * BUFF;
            const float* Ahi = buf;
            const float* Alo = buf + OFF_ALO;
            const float* Bhi = buf + OFF_BHI;
            const float* Blo = buf + OFF_BLO;

            // Prefetch next tile gmem -> regs (hidden behind MMA compute)
            if (t < NTILES - 1) {
                const int k0 = (t + 1) * TBK;
                xa = *(const float4*)&x[(mBase + rowA) * INPUT_DIM + k0 + kcA];
#pragma unroll
                for (int l = 0; l < 2; l++)
                    wb[l] = *(const float4*)&W[(nBase + rowB[l]) * INPUT_DIM + k0 + kcB[l]];
            }

#pragma unroll
            for (int s = 0; s < 4; s++) {        // 4 k8 steps per tile
                const int ka = s * 8 + q;
                const uint32_t a0h = __float_as_uint(Ahi[ar0 + ka]);
                const uint32_t a1h = __float_as_uint(Ahi[ar1 + ka]);
                const uint32_t a2h = __float_as_uint(Ahi[ar0 + ka + 4]);
                const uint32_t a3h = __float_as_uint(Ahi[ar1 + ka + 4]);
                const uint32_t a0l = __float_as_uint(Alo[ar0 + ka]);
                const uint32_t a1l = __float_as_uint(Alo[ar1 + ka]);
                const uint32_t a2l = __float_as_uint(Alo[ar0 + ka + 4]);
                const uint32_t a3l = __float_as_uint(Alo[ar1 + ka + 4]);

                float (*cm)[4] = (s & 1) ? c1 : c0;

#pragma unroll
                for (int nb = 0; nb < 2; nb++) {
                    const int rb = (nh * 16 + nb * 8 + g) * ROWF + ka;
                    const uint32_t b0h = __float_as_uint(Bhi[rb]);
                    const uint32_t b1h = __float_as_uint(Bhi[rb + 4]);
                    const uint32_t b0l = __float_as_uint(Blo[rb]);
                    const uint32_t b1l = __float_as_uint(Blo[rb + 4]);

                    mma_tf32(cm[nb], a0h, a1h, a2h, a3h, b0h, b1h);  // hi*hi
                    mma_tf32(cx[nb], a0h, a1h, a2h, a3h, b0l, b1l);  // hi*lo
                    mma_tf32(cx[nb], a0l, a1l, a2l, a3l, b0h, b1h);  // lo*hi
                }
            }

            // Split+store prefetched tile into the other buffer, then sync
            if (t < NTILES - 1) {
                float* nbuf = sm + ((t + 1) & 1) * BUFF;
                cvt_store(nbuf, nbuf + OFF_ALO, rowA * ROWF + kcA, xa);
#pragma unroll
                for (int l = 0; l < 2; l++)
                    cvt_store(nbuf + OFF_BHI, nbuf + OFF_BLO,
                              rowB[l] * ROWF + kcB[l], wb[l]);
                __syncthreads();
            }
        }

        // Epilogue: combine (RN), bias + sigmoid.
        const int m1 = mBase + mb * 16 + g;
        const int m2 = m1 + 8;
#pragma unroll
        for (int nb = 0; nb < 2; nb++) {
            const int col = nBase + nh * 16 + nb * 8 + 2 * q;
            const float2 bb = *(const float2*)&bias[col];

            const float z0 = (c0[nb][0] + c1[nb][0]) + cx[nb][0] + bb.x;
            const float z1 = (c0[nb][1] + c1[nb][1]) + cx[nb][1] + bb.y;
            const float z2 = (c0[nb][2] + c1[nb][2]) + cx[nb][2] + bb.x;
            const float z3 = (c0[nb][3] + c1[nb][3]) + cx[nb][3] + bb.y;

            float2 o1, o2;
            o1.x = 1.0f / (1.0f + __expf(-z0));
            o1.y = 1.0f / (1.0f + __expf(-z1));
            o2.x = 1.0f / (1.0f + __expf(-z2));
            o2.y = 1.0f / (1.0f + __expf(-z3));

            *(float2*)&rates[m1 * NUM_NEURONS + col] = o1;
            *(float2*)&rates[m2 * NUM_NEURONS + col] = o2;
        }

        // Release this m-tile: all block stores ordered by the bar, then a
        // gpu-scope release-add that spike consumers acquire on.
        __syncthreads();
        if (tid == 0)
            asm volatile("red.release.gpu.global.add.u32 [%0], %1;"
                         :: "l"(g_cnt + mtile), "r"(1u) : "memory");
        __syncthreads();   // keep warps together before smem reuse next pass
    }
}

// ---------------------------------------------------------------------------
// Kernel B: streaming spike compare, co-scheduled with the GEMM via PDL.
// grid (T, BATCH), 256 threads; one (b,t) neuron row per block.
// u loads issued first (prefetch while spinning); thread 0 acquire-spins on
// the m-tile counter; rates read via __ldcg (L2-coherent) after the bar.
// ---------------------------------------------------------------------------
__global__ __launch_bounds__(256)
void spike_kernel(const float4* __restrict__ u,
                  const float4* __restrict__ rates,
                  float4* __restrict__ spikes) {
    const int b = blockIdx.y;
    const long long base = (long long)(b * TIME_STEPS + blockIdx.x) * (NUM_NEURONS / 4);
    const int j = threadIdx.x * 2;

    const float4 u0 = __ldcs(&u[base + j]);
    const float4 u1 = __ldcs(&u[base + j + 1]);

    // Wait for this batch row's rates (m-tile of 32 rows, 32 n-block arrivals)
    if (threadIdx.x == 0) {
        const int mtile = b >> 5;
        unsigned v;
        do {
            asm volatile("ld.acquire.gpu.global.u32 %0, [%1];"
                         : "=r"(v) : "l"(g_cnt + mtile) : "memory");
            if (v < 32u) __nanosleep(256);
        } while (v < 32u);
    }
    __syncthreads();

    const float4* rrow = rates + b * (NUM_NEURONS / 4);
    const float4 r0 = __ldcg(&rrow[j]);
    const float4 r1 = __ldcg(&rrow[j + 1]);

    float4 s0, s1;
    s0.x = (u0.x < r0.x) ? 1.0f : 0.0f;
    s0.y = (u0.y < r0.y) ? 1.0f : 0.0f;
    s0.z = (u0.z < r0.z) ? 1.0f : 0.0f;
    s0.w = (u0.w < r0.w) ? 1.0f : 0.0f;
    s1.x = (u1.x < r1.x) ? 1.0f : 0.0f;
    s1.y = (u1.y < r1.y) ? 1.0f : 0.0f;
    s1.z = (u1.z < r1.z) ? 1.0f : 0.0f;
    s1.w = (u1.w < r1.w) ? 1.0f : 0.0f;

    __stcs(&spikes[base + j], s0);
    __stcs(&spikes[base + j + 1], s1);
}

extern "C" void kernel_launch(void* const* d_in, const int* in_sizes, int n_in,
                              void* d_out, int out_size) {
    const float* x = (const float*)d_in[0];
    const float* W = (const float*)d_in[1];
    const float* b = (const float*)d_in[2];
    const float* u = (const float*)d_in[3];

    float* out    = (float*)d_out;
    float* spikes = out;                                               // 52,428,800
    float* rates  = out + (long long)BATCH * TIME_STEPS * NUM_NEURONS; // +524,288

    cudaFuncSetAttribute(rates_kernel,
                         cudaFuncAttributeMaxDynamicSharedMemorySize, SMEM_BYTES);

    // 0) zero the release counters (stream-ordered before the GEMM)
    reset_kernel<<<1, 32>>>();

    // 1) tensor-core rates GEMM (PLC fires at its start)
    dim3 gridA(NUM_NEURONS / TBN, 4);             // (32, 4) = 128 blocks
    rates_kernel<<<gridA, 256, SMEM_BYTES>>>(x, W, b, rates);

    // 2) spike stream, PDL-launched so it co-schedules with the GEMM;
    //    flag spins provide the actual data dependency.
    const float4* u4 = (const float4*)u;
    const float4* r4 = (const float4*)rates;
    float4*       s4 = (float4*)spikes;

    cudaLaunchConfig_t cfg = {};
    cfg.gridDim  = dim3(TIME_STEPS, BATCH, 1);    // (100, 256)
    cfg.blockDim = dim3(256, 1, 1);
    cfg.dynamicSmemBytes = 0;
    cfg.stream = 0;
    cudaLaunchAttribute attrs[1];
    attrs[0].id = cudaLaunchAttributeProgrammaticStreamSerialization;
    attrs[0].val.programmaticStreamSerializationAllowed = 1;
    cfg.attrs = attrs;
    cfg.numAttrs = 1;

    cudaError_t e = cudaLaunchKernelEx(&cfg, spike_kernel, u4, r4, s4);
    if (e != cudaSuccess) {
        (void)cudaGetLastError();  // clear; plain launch (flags already ==32)
        spike_kernel<<<dim3(TIME_STEPS, BATCH, 1), 256>>>(u4, r4, s4);
    }
}

// round 13
// speedup vs baseline: 1.1435x; 1.1435x over previous
#include <cuda_runtime.h>
#include <cuda_bf16.h>
#include <cstdint>

// SpikeEncoder: rates = sigmoid(x @ W^T + b); spikes = (u < rates)
// x: [256,512] f32, W: [2048,512] f32, b: [2048] f32, u: [256,100,2048] f32
// out: spikes [256*100*2048] f32, then rates [256*2048] f32

#define BATCH 256
#define INPUT_DIM 512
#define NUM_NEURONS 2048
#define TIME_STEPS 100

#define MCHUNK 64                  // batch rows per pipeline chunk
#define NCHUNKS 4

#define TBM 32                     // GEMM tile rows
#define TBN 64
#define TBK 32
#define NTILES (INPUT_DIM / TBK)   // 16

#define ROWF 36                    // padded floats per smem row (bank-bijective)
#define TILEF_A (TBM * ROWF)       // 1152
#define TILEF_B (TBN * ROWF)       // 2304
#define OFF_ALO  TILEF_A
#define OFF_BHI  (2 * TILEF_A)
#define OFF_BLO  (2 * TILEF_A + TILEF_B)
#define BUFF (2 * TILEF_A + 2 * TILEF_B)   // 6912 floats
#define SMEM_BYTES (2 * BUFF * 4)          // 55296 bytes

// fp32 -> tf32 split via mantissa mask: hi = one LOP3 (exact, hi+lo == v);
// lo rounded to tf32 (cvt.rna) -> representation err ~2^-21|v|.
__device__ __forceinline__ void tf32_split(float v, float& h, float& l) {
    const float hf = __uint_as_float(__float_as_uint(v) & 0xFFFFE000u);
    uint32_t lb;
    asm("cvt.rna.tf32.f32 %0, %1;" : "=r"(lb) : "f"(v - hf));
    h = hf;
    l = __uint_as_float(lb);
}

__device__ __forceinline__ void cvt_store(float* __restrict__ hi,
                                          float* __restrict__ lo,
                                          int off, float4 v) {
    float4 h, l;
    tf32_split(v.x, h.x, l.x);
    tf32_split(v.y, h.y, l.y);
    tf32_split(v.z, h.z, l.z);
    tf32_split(v.w, h.w, l.w);
    *(float4*)&hi[off] = h;
    *(float4*)&lo[off] = l;
}

// D += A(tf32, m16k8 row) x B(tf32, k8n8 col)
__device__ __forceinline__ void mma_tf32(float c[4],
                                         uint32_t a0, uint32_t a1,
                                         uint32_t a2, uint32_t a3,
                                         uint32_t b0, uint32_t b1) {
    asm volatile(
        "mma.sync.aligned.m16n8k8.row.col.f32.tf32.tf32.f32 "
        "{%0,%1,%2,%3}, {%4,%5,%6,%7}, {%8,%9}, {%0,%1,%2,%3};"
        : "+f"(c[0]), "+f"(c[1]), "+f"(c[2]), "+f"(c[3])
        : "r"(a0), "r"(a1), "r"(a2), "r"(a3), "r"(b0), "r"(b1));
}

// ---------------------------------------------------------------------------
// GEMM chunk: rates[mBase0 .. mBase0+63] = sigmoid(x @ W^T + b).
// 32x64 tile, grid (32, 2) = 64 blocks, 256 threads, 8 warps
// (mb = w&1 m16-blocks, nh = w>>1 n16 groups). tf32 MMA, 3-term
// compensation; hi*hi split even/odd-k8 (c0/c1) vs RZ bias; cross terms
// in cx; RN combine at epilogue. Double-buffered smem, split-at-store.
// (Exact math of the R12 GEMM, which verified at rel_err 3.9e-4.)
// ---------------------------------------------------------------------------
__global__ __launch_bounds__(256)
void rates_chunk_kernel(const float* __restrict__ x,
                        const float* __restrict__ W,
                        const float* __restrict__ bias,
                        float* __restrict__ rates,
                        int mBase0) {
    extern __shared__ float sm[];

    const int tid  = threadIdx.x;
    const int warp = tid >> 5;
    const int lane = tid & 31;
    const int g = lane >> 2;
    const int q = lane & 3;
    const int mb = warp & 1;       // m16 block (0..1)
    const int nh = warp >> 1;      // n16 group (0..3)

    const int nBase = blockIdx.x * TBN;
    const int mBase = mBase0 + blockIdx.y * TBM;

    // Cooperative-load coords. A: 256 float4/tile (1/thread); B: 512 (2/thread)
    const int rowA = tid >> 3;             // 0..31
    const int kcA  = (tid & 7) * 4;
    int rowB[2], kcB[2];
#pragma unroll
    for (int l = 0; l < 2; l++) {
        const int f = tid + l * 256;
        rowB[l] = f >> 3;                  // 0..63
        kcB[l]  = (f & 7) * 4;
    }

    const int ar0 = (mb * 16 + g) * ROWF;
    const int ar1 = ar0 + 8 * ROWF;

    // Prologue: tile 0 -> regs -> split -> smem buf 0
    float4 xa = *(const float4*)&x[(mBase + rowA) * INPUT_DIM + kcA];
    float4 wb[2];
#pragma unroll
    for (int l = 0; l < 2; l++)
        wb[l] = *(const float4*)&W[(nBase + rowB[l]) * INPUT_DIM + kcB[l]];
    {
        float* buf = sm;
        cvt_store(buf, buf + OFF_ALO, rowA * ROWF + kcA, xa);
#pragma unroll
        for (int l = 0; l < 2; l++)
            cvt_store(buf + OFF_BHI, buf + OFF_BLO, rowB[l] * ROWF + kcB[l], wb[l]);
    }
    __syncthreads();

    float c0[2][4], c1[2][4], cx[2][4];
#pragma unroll
    for (int nb = 0; nb < 2; nb++)
#pragma unroll
        for (int e = 0; e < 4; e++) { c0[nb][e] = 0.f; c1[nb][e] = 0.f; cx[nb][e] = 0.f; }

    for (int t = 0; t < NTILES; t++) {
        const float* buf = sm + (t & 1) * BUFF;
        const float* Ahi = buf;
        const float* Alo = buf + OFF_ALO;
        const float* Bhi = buf + OFF_BHI;
        const float* Blo = buf + OFF_BLO;

        if (t < NTILES - 1) {
            const int k0 = (t + 1) * TBK;
            xa = *(const float4*)&x[(mBase + rowA) * INPUT_DIM + k0 + kcA];
#pragma unroll
            for (int l = 0; l < 2; l++)
                wb[l] = *(const float4*)&W[(nBase + rowB[l]) * INPUT_DIM + k0 + kcB[l]];
        }

#pragma unroll
        for (int s = 0; s < 4; s++) {
            const int ka = s * 8 + q;
            const uint32_t a0h = __float_as_uint(Ahi[ar0 + ka]);
            const uint32_t a1h = __float_as_uint(Ahi[ar1 + ka]);
            const uint32_t a2h = __float_as_uint(Ahi[ar0 + ka + 4]);
            const uint32_t a3h = __float_as_uint(Ahi[ar1 + ka + 4]);
            const uint32_t a0l = __float_as_uint(Alo[ar0 + ka]);
            const uint32_t a1l = __float_as_uint(Alo[ar1 + ka]);
            const uint32_t a2l = __float_as_uint(Alo[ar0 + ka + 4]);
            const uint32_t a3l = __float_as_uint(Alo[ar1 + ka + 4]);

            float (*cm)[4] = (s & 1) ? c1 : c0;

#pragma unroll
            for (int nb = 0; nb < 2; nb++) {
                const int rb = (nh * 16 + nb * 8 + g) * ROWF + ka;
                const uint32_t b0h = __float_as_uint(Bhi[rb]);
                const uint32_t b1h = __float_as_uint(Bhi[rb + 4]);
                const uint32_t b0l = __float_as_uint(Blo[rb]);
                const uint32_t b1l = __float_as_uint(Blo[rb + 4]);

                mma_tf32(cm[nb], a0h, a1h, a2h, a3h, b0h, b1h);  // hi*hi
                mma_tf32(cx[nb], a0h, a1h, a2h, a3h, b0l, b1l);  // hi*lo
                mma_tf32(cx[nb], a0l, a1l, a2l, a3l, b0h, b1h);  // lo*hi
            }
        }

        if (t < NTILES - 1) {
            float* nbuf = sm + ((t + 1) & 1) * BUFF;
            cvt_store(nbuf, nbuf + OFF_ALO, rowA * ROWF + kcA, xa);
#pragma unroll
            for (int l = 0; l < 2; l++)
                cvt_store(nbuf + OFF_BHI, nbuf + OFF_BLO,
                          rowB[l] * ROWF + kcB[l], wb[l]);
            __syncthreads();
        }
    }

    // Epilogue: combine (RN), bias + sigmoid.
    const int m1 = mBase + mb * 16 + g;
    const int m2 = m1 + 8;
#pragma unroll
    for (int nb = 0; nb < 2; nb++) {
        const int col = nBase + nh * 16 + nb * 8 + 2 * q;
        const float2 bb = *(const float2*)&bias[col];

        const float z0 = (c0[nb][0] + c1[nb][0]) + cx[nb][0] + bb.x;
        const float z1 = (c0[nb][1] + c1[nb][1]) + cx[nb][1] + bb.y;
        const float z2 = (c0[nb][2] + c1[nb][2]) + cx[nb][2] + bb.x;
        const float z3 = (c0[nb][3] + c1[nb][3]) + cx[nb][3] + bb.y;

        float2 o1, o2;
        o1.x = 1.0f / (1.0f + __expf(-z0));
        o1.y = 1.0f / (1.0f + __expf(-z1));
        o2.x = 1.0f / (1.0f + __expf(-z2));
        o2.y = 1.0f / (1.0f + __expf(-z3));

        *(float2*)&rates[m1 * NUM_NEURONS + col] = o1;
        *(float2*)&rates[m2 * NUM_NEURONS + col] = o2;
    }
}

// ---------------------------------------------------------------------------
// Spike chunk: b in [b0, b0+63]. grid (T, 64), 256 threads; one (b,t)
// neuron row per block (the proven 74%-of-DRAM shape). Plain stream
// ordering after its GEMM chunk — no PDL, no flags.
// ---------------------------------------------------------------------------
__global__ __launch_bounds__(256)
void spike_chunk_kernel(const float4* __restrict__ u,
                        const float4* __restrict__ rates,
                        float4* __restrict__ spikes,
                        int b0) {
    const int b = b0 + blockIdx.y;
    const long long base = (long long)(b * TIME_STEPS + blockIdx.x) * (NUM_NEURONS / 4);
    const int j = threadIdx.x * 2;

    const float4 u0 = __ldcs(&u[base + j]);
    const float4 u1 = __ldcs(&u[base + j + 1]);

    const float4* rrow = rates + b * (NUM_NEURONS / 4);
    const float4 r0 = __ldg(&rrow[j]);
    const float4 r1 = __ldg(&rrow[j + 1]);

    float4 s0, s1;
    s0.x = (u0.x < r0.x) ? 1.0f : 0.0f;
    s0.y = (u0.y < r0.y) ? 1.0f : 0.0f;
    s0.z = (u0.z < r0.z) ? 1.0f : 0.0f;
    s0.w = (u0.w < r0.w) ? 1.0f : 0.0f;
    s1.x = (u1.x < r1.x) ? 1.0f : 0.0f;
    s1.y = (u1.y < r1.y) ? 1.0f : 0.0f;
    s1.z = (u1.z < r1.z) ? 1.0f : 0.0f;
    s1.w = (u1.w < r1.w) ? 1.0f : 0.0f;

    __stcs(&spikes[base + j], s0);
    __stcs(&spikes[base + j + 1], s1);
}

extern "C" void kernel_launch(void* const* d_in, const int* in_sizes, int n_in,
                              void* d_out, int out_size) {
    const float* x = (const float*)d_in[0];
    const float* W = (const float*)d_in[1];
    const float* b = (const float*)d_in[2];
    const float* u = (const float*)d_in[3];

    float* out    = (float*)d_out;
    float* spikes = out;                                               // 52,428,800
    float* rates  = out + (long long)BATCH * TIME_STEPS * NUM_NEURONS; // +524,288

    // Lazy one-time creation of side streams + events (host objects only;
    // no device memory). Captured graphs get real parallel branches.
    static cudaStream_t s[NCHUNKS - 1];
    static cudaEvent_t  eFork, eJoin[NCHUNKS - 1];
    static bool inited = false;
    if (!inited) {
        for (int i = 0; i < NCHUNKS - 1; i++)
            cudaStreamCreateWithFlags(&s[i], cudaStreamNonBlocking);
        cudaEventCreateWithFlags(&eFork, cudaEventDisableTiming);
        for (int i = 0; i < NCHUNKS - 1; i++)
            cudaEventCreateWithFlags(&eJoin[i], cudaEventDisableTiming);
        cudaFuncSetAttribute(rates_chunk_kernel,
                             cudaFuncAttributeMaxDynamicSharedMemorySize, SMEM_BYTES);
        inited = true;
    }

    const float4* u4 = (const float4*)u;
    const float4* r4 = (const float4*)rates;
    float4*       s4 = (float4*)spikes;

    // Fork: side streams branch off the main (capture) stream.
    cudaEventRecord(eFork, 0);
    for (int i = 0; i < NCHUNKS - 1; i++)
        cudaStreamWaitEvent(s[i], eFork, 0);

    // Chunk 0 on the main stream; chunks 1..3 on side streams.
    // All GEMM chunks issue immediately (independent); each spike chunk is
    // stream-ordered after its own GEMM chunk.
    dim3 gGrid(NUM_NEURONS / TBN, MCHUNK / TBM);   // (32, 2) = 64 blocks
    dim3 sGrid(TIME_STEPS, MCHUNK);                // (100, 64)

    rates_chunk_kernel<<<gGrid, 256, SMEM_BYTES, 0>>>(x, W, b, rates, 0);
    for (int i = 1; i < NCHUNKS; i++)
        rates_chunk_kernel<<<gGrid, 256, SMEM_BYTES, s[i - 1]>>>(
            x, W, b, rates, i * MCHUNK);

    spike_chunk_kernel<<<sGrid, 256, 0, 0>>>(u4, r4, s4, 0);
    for (int i = 1; i < NCHUNKS; i++)
        spike_chunk_kernel<<<sGrid, 256, 0, s[i - 1]>>>(u4, r4, s4, i * MCHUNK);

    // Join: main stream waits for all side branches.
    for (int i = 0; i < NCHUNKS - 1; i++) {
        cudaEventRecord(eJoin[i], s[i]);
        cudaStreamWaitEvent(0, eJoin[i], 0);
    }
}